// round 15
// baseline (speedup 1.0000x reference)
#include <cuda_runtime.h>
#include <cuda_bf16.h>
#include <cstdint>
#include <math.h>

#define SQ   2048
#define HDIM 2048
#define NH   16
#define NKV  8
#define HD   128
#define FF   8192

typedef __nv_bfloat16 bf16;

// ---------------- scratch (device globals; no allocs allowed) ----------------
__device__ float g_qf[SQ * NH * HD];
__device__ float g_kf[SQ * NKV * HD];
__device__ float g_gate2[2048 * FF];
__device__ float g_up2[2048 * FF];

__device__ bf16 g_h1h[SQ * HDIM],  g_h1l[SQ * HDIM];
__device__ bf16 g_oh[SQ * HDIM],   g_ol[SQ * HDIM];
__device__ bf16 g_gh2[2048 * FF],  g_gl2[2048 * FF];
__device__ int  g_gidx[2048];

__device__ bf16 g_qh[SQ * NH * HD],  g_ql[SQ * NH * HD];
__device__ bf16 g_kh[SQ * NKV * HD], g_kl[SQ * NKV * HD];
__device__ bf16 g_vh[SQ * NKV * HD], g_vl[SQ * NKV * HD];

// transposed weights [N][K], hi/lo
__device__ bf16 g_wqh[HDIM * HDIM], g_wql[HDIM * HDIM];
__device__ bf16 g_wkh[1024 * HDIM], g_wkl[1024 * HDIM];
__device__ bf16 g_wvh[1024 * HDIM], g_wvl[1024 * HDIM];
__device__ bf16 g_woh[HDIM * HDIM], g_wol[HDIM * HDIM];
__device__ bf16 g_w1h[FF * HDIM],   g_w1l[FF * HDIM];
__device__ bf16 g_w3h[FF * HDIM],   g_w3l[FF * HDIM];
__device__ bf16 g_v1h[FF * HDIM],   g_v1l[FF * HDIM];
__device__ bf16 g_v3h[FF * HDIM],   g_v3l[FF * HDIM];
__device__ bf16 g_w2h[HDIM * FF],   g_w2l[HDIM * FF];
__device__ bf16 g_v2h[HDIM * FF],   g_v2l[HDIM * FF];

// ---------------- helpers ----------------
__device__ __forceinline__ uint32_t smem_to_u32(const void* p) {
    uint32_t a;
    asm("{ .reg .u64 t; cvta.to.shared.u64 t, %1; cvt.u32.u64 %0, t; }" : "=r"(a) : "l"(p));
    return a;
}
__device__ __forceinline__ void ldmatrix_x4(uint32_t* r, uint32_t addr) {
    asm volatile("ldmatrix.sync.aligned.m8n8.x4.shared.b16 {%0,%1,%2,%3}, [%4];"
        : "=r"(r[0]), "=r"(r[1]), "=r"(r[2]), "=r"(r[3]) : "r"(addr));
}
__device__ __forceinline__ void ldmatrix_x2(uint32_t* r, uint32_t addr) {
    asm volatile("ldmatrix.sync.aligned.m8n8.x2.shared.b16 {%0,%1}, [%2];"
        : "=r"(r[0]), "=r"(r[1]) : "r"(addr));
}
__device__ __forceinline__ void ldmatrix_x2_trans(uint32_t* r, uint32_t addr) {
    asm volatile("ldmatrix.sync.aligned.m8n8.x2.trans.shared.b16 {%0,%1}, [%2];"
        : "=r"(r[0]), "=r"(r[1]) : "r"(addr));
}
__device__ __forceinline__ void mma_bf16(float* c, const uint32_t* a, const uint32_t* b) {
    asm volatile(
        "mma.sync.aligned.m16n8k16.row.col.f32.bf16.bf16.f32 "
        "{%0,%1,%2,%3}, {%4,%5,%6,%7}, {%8,%9}, {%0,%1,%2,%3};"
        : "+f"(c[0]), "+f"(c[1]), "+f"(c[2]), "+f"(c[3])
        : "r"(a[0]), "r"(a[1]), "r"(a[2]), "r"(a[3]), "r"(b[0]), "r"(b[1]));
}
__device__ __forceinline__ void cp_async16(uint32_t dst, const void* src) {
    asm volatile("cp.async.cg.shared.global [%0], [%1], 16;" :: "r"(dst), "l"(src));
}
#define CP_COMMIT() asm volatile("cp.async.commit_group;" ::: "memory")
#define CP_WAIT2()  asm volatile("cp.async.wait_group 2;" ::: "memory")
#define CP_WAIT1()  asm volatile("cp.async.wait_group 1;" ::: "memory")
#define CP_WAIT0()  asm volatile("cp.async.wait_group 0;" ::: "memory")

__device__ __forceinline__ uint32_t pack2bf(float x, float y) {
    __nv_bfloat16 bx = __float2bfloat16(x), by = __float2bfloat16(y);
    return ((uint32_t)__bfloat16_as_ushort(by) << 16) | (uint32_t)__bfloat16_as_ushort(bx);
}

// ---------------- weight convert (R9): W[K][N] fp32 -> th,tl [N][K] bf16 ----------------
__global__ void __launch_bounds__(256) wconvert_kernel(
    const float* __restrict__ W, bf16* __restrict__ th,
    bf16* __restrict__ tl, int Kd, int Nd) {
    __shared__ float t[64][65];
    const int kb = blockIdx.y * 64, nb = blockIdx.x * 64;
    const int tx = threadIdx.x & 15, ty = threadIdx.x >> 4;
#pragma unroll
    for (int i = 0; i < 4; i++) {
        int r = ty + i * 16;
        float4 v = *(const float4*)&W[(size_t)(kb + r) * Nd + nb + tx * 4];
        t[r][tx * 4 + 0] = v.x;
        t[r][tx * 4 + 1] = v.y;
        t[r][tx * 4 + 2] = v.z;
        t[r][tx * 4 + 3] = v.w;
    }
    __syncthreads();
    const int n = threadIdx.x >> 2, kc = (threadIdx.x & 3) * 16;
    uint32_t hv[8], lv[8];
#pragma unroll
    for (int j = 0; j < 8; j++) {
        float a = t[kc + 2 * j][n], b = t[kc + 2 * j + 1][n];
        bf16 ha = __float2bfloat16(a), hb = __float2bfloat16(b);
        hv[j] = ((uint32_t)__bfloat16_as_ushort(hb) << 16) | __bfloat16_as_ushort(ha);
        lv[j] = pack2bf(a - __bfloat162float(ha), b - __bfloat162float(hb));
    }
    size_t o = (size_t)(nb + n) * Kd + kb + kc;
    *(uint4*)(th + o)     = make_uint4(hv[0], hv[1], hv[2], hv[3]);
    *(uint4*)(th + o + 8) = make_uint4(hv[4], hv[5], hv[6], hv[7]);
    *(uint4*)(tl + o)     = make_uint4(lv[0], lv[1], lv[2], lv[3]);
    *(uint4*)(tl + o + 8) = make_uint4(lv[4], lv[5], lv[6], lv[7]);
}

// ---------------- GEMM core: 128 threads, 4 warps (2x2), warp tile 64x64 ----------------
// Swizzled smem (64B rows, XOR chunk swizzle), 3-stage cp.async pipeline.
#define ARR   8192                     // 128 rows * 64B
#define STAGE 32768                    // 4 arrays
#define GSMEM (3 * STAGE + 1024)       // 99328

// physical byte offset of (row, 16B-chunk) within one operand array
#define SWZ(row, chunk) ((uint32_t)(((row) << 6) + ((((chunk) ^ (((row) >> 1) & 3))) << 4)))

__device__ __forceinline__ void gemm_core(
    const bf16* __restrict__ Ahg, const bf16* __restrict__ Alg,
    const bf16* __restrict__ Bhg, const bf16* __restrict__ Blg,
    float* __restrict__ C, int N, int K, int m0, int n0,
    const int* __restrict__ arow, const int* __restrict__ crow,
    const float* __restrict__ cadd, char* smc,
    bf16* __restrict__ Chh, bf16* __restrict__ Cll)
{
    const uint32_t base = smem_to_u32(smc);
    int* rowA = (int*)(smc + 3 * STAGE);
    int* rowC = (int*)(smc + 3 * STAGE + 512);
    const int tid = threadIdx.x, lane = tid & 31, wid = tid >> 5;
    const int wm = wid & 1, wn = wid >> 1;

    rowA[tid] = arow ? arow[m0 + tid] : (m0 + tid);
    rowC[tid] = crow ? crow[m0 + tid] : (m0 + tid);
    __syncthreads();

    float acc[4][8][4];
#pragma unroll
    for (int i = 0; i < 4; i++)
#pragma unroll
        for (int j = 0; j < 8; j++)
#pragma unroll
            for (int q = 0; q < 4; q++) acc[i][j][q] = 0.f;

    const int a_row = lane & 15;
    const int a_ch  = lane >> 4;              // 0 or 1 (chunk within k16 step)
    const int b4_row = (lane & 7) + ((lane >> 4) << 3);
    const int b4_ch  = (lane >> 3) & 1;
    const int niter = K >> 5;

#define LOAD_STAGE(IT, B) do { \
    int k0_ = (IT) * 32; \
    uint32_t s_ = base + (B) * STAGE; \
    _Pragma("unroll") \
    for (int c = tid; c < 512; c += 128) { \
        int row_ = c >> 2, ch_ = c & 3; \
        int ko_ = ch_ << 3; \
        size_t asrc_ = (size_t)rowA[row_] * K + k0_ + ko_; \
        size_t bsrc_ = (size_t)(n0 + row_) * K + k0_ + ko_; \
        uint32_t d_ = s_ + SWZ(row_, ch_); \
        cp_async16(d_,           Ahg + asrc_); \
        cp_async16(d_ + ARR,     Alg + asrc_); \
        cp_async16(d_ + 2 * ARR, Bhg + bsrc_); \
        cp_async16(d_ + 3 * ARR, Blg + bsrc_); \
    } } while (0)

    LOAD_STAGE(0, 0);
    CP_COMMIT();
    LOAD_STAGE(1, 1);
    CP_COMMIT();

    for (int it = 0; it < niter; it++) {
        const int b = it % 3;
        if (it + 2 < niter) { LOAD_STAGE(it + 2, (it + 2) % 3); CP_COMMIT(); CP_WAIT2(); }
        else if (it + 1 < niter) { CP_WAIT1(); }
        else { CP_WAIT0(); }
        __syncthreads();
        const uint32_t Ah_s = base + b * STAGE, Al_s = Ah_s + ARR;
        const uint32_t Bh_s = Ah_s + 2 * ARR,   Bl_s = Ah_s + 3 * ARR;
#pragma unroll
        for (int ks = 0; ks < 2; ks++) {
            uint32_t aH[4][4], aL[4][4];
#pragma unroll
            for (int mi = 0; mi < 4; mi++) {
                int row = wm * 64 + mi * 16 + a_row;
                uint32_t off = SWZ(row, ks * 2 + a_ch);
                ldmatrix_x4(aH[mi], Ah_s + off);
                ldmatrix_x4(aL[mi], Al_s + off);
            }
#pragma unroll
            for (int nip = 0; nip < 4; nip++) {
                uint32_t bH[4], bL[4];
                int row = wn * 64 + nip * 16 + b4_row;
                uint32_t off = SWZ(row, ks * 2 + b4_ch);
                ldmatrix_x4(bH, Bh_s + off);
                ldmatrix_x4(bL, Bl_s + off);
#pragma unroll
                for (int mi = 0; mi < 4; mi++) {
                    mma_bf16(acc[mi][nip * 2 + 0], aH[mi], bH + 0);
                    mma_bf16(acc[mi][nip * 2 + 0], aH[mi], bL + 0);
                    mma_bf16(acc[mi][nip * 2 + 0], aL[mi], bH + 0);
                    mma_bf16(acc[mi][nip * 2 + 1], aH[mi], bH + 2);
                    mma_bf16(acc[mi][nip * 2 + 1], aH[mi], bL + 2);
                    mma_bf16(acc[mi][nip * 2 + 1], aL[mi], bH + 2);
                }
            }
        }
        __syncthreads();
    }
#undef LOAD_STAGE

    const int g = lane >> 2, t = lane & 3;
#pragma unroll
    for (int mi = 0; mi < 4; mi++) {
#pragma unroll
        for (int half = 0; half < 2; half++) {
            int rl = wm * 64 + mi * 16 + g + half * 8;
            int orow = rowC[rl];
            if (Chh) {
                bf16* Hp = Chh + (size_t)orow * N + n0;
                bf16* Lp = Cll + (size_t)orow * N + n0;
#pragma unroll
                for (int ni = 0; ni < 8; ni++) {
                    int col = wn * 64 + ni * 8 + t * 2;
                    float v0 = acc[mi][ni][half * 2 + 0];
                    float v1 = acc[mi][ni][half * 2 + 1];
                    bf16 h0 = __float2bfloat16(v0), h1 = __float2bfloat16(v1);
                    *(uint32_t*)(Hp + col) = ((uint32_t)__bfloat16_as_ushort(h1) << 16) | __bfloat16_as_ushort(h0);
                    *(uint32_t*)(Lp + col) = pack2bf(v0 - __bfloat162float(h0), v1 - __bfloat162float(h1));
                }
            } else {
                float* Cp = C + (size_t)orow * N + n0;
                const float* ap = cadd ? (cadd + (size_t)(m0 + rl) * N + n0) : nullptr;
#pragma unroll
                for (int ni = 0; ni < 8; ni++) {
                    int col = wn * 64 + ni * 8 + t * 2;
                    float2 v;
                    v.x = acc[mi][ni][half * 2 + 0];
                    v.y = acc[mi][ni][half * 2 + 1];
                    if (ap) { v.x += ap[col]; v.y += ap[col + 1]; }
                    *(float2*)(Cp + col) = v;
                }
            }
        }
    }
}

// ---------------- generic GEMM (used for WO) ----------------
__global__ void __launch_bounds__(128, 2) tgemm_kernel(
    const bf16* __restrict__ Ahg, const bf16* __restrict__ Alg,
    const bf16* __restrict__ Bhg, const bf16* __restrict__ Blg,
    float* __restrict__ C, int N, int K,
    const int* __restrict__ arow, const int* __restrict__ crow,
    const float* __restrict__ cadd)
{
    extern __shared__ char smc[];
    gemm_core(Ahg, Alg, Bhg, Blg, C, N, K, blockIdx.y * 128, blockIdx.x * 128,
              arow, crow, cadd, smc, nullptr, nullptr);
}

// ---------------- fused QKV GEMM: grid (32, 16); V writes bf16 hi/lo directly ----------------
__global__ void __launch_bounds__(128, 2) qkv_kernel(
    const bf16* __restrict__ Ahg, const bf16* __restrict__ Alg,
    const bf16* __restrict__ wqh, const bf16* __restrict__ wql,
    const bf16* __restrict__ wkh, const bf16* __restrict__ wkl,
    const bf16* __restrict__ wvh, const bf16* __restrict__ wvl,
    float* __restrict__ qf, float* __restrict__ kf,
    bf16* __restrict__ vh, bf16* __restrict__ vl)
{
    extern __shared__ char smc[];
    const int bx = blockIdx.x;
    if (bx < 16) {
        gemm_core(Ahg, Alg, wqh, wql, qf, 2048, HDIM, blockIdx.y * 128, bx * 128,
                  nullptr, nullptr, nullptr, smc, nullptr, nullptr);
    } else if (bx < 24) {
        gemm_core(Ahg, Alg, wkh, wkl, kf, 1024, HDIM, blockIdx.y * 128, (bx - 16) * 128,
                  nullptr, nullptr, nullptr, smc, nullptr, nullptr);
    } else {
        gemm_core(Ahg, Alg, wvh, wvl, nullptr, 1024, HDIM, blockIdx.y * 128, (bx - 24) * 128,
                  nullptr, nullptr, nullptr, smc, vh, vl);
    }
}

// ---------------- fused FFN gate/up GEMM: grid (128, 16) ----------------
__global__ void __launch_bounds__(128, 2) ffn_kernel(
    const bf16* __restrict__ Ahg, const bf16* __restrict__ Alg,
    const bf16* __restrict__ v1h, const bf16* __restrict__ v1l,
    const bf16* __restrict__ v3h, const bf16* __restrict__ v3l,
    const bf16* __restrict__ w1h, const bf16* __restrict__ w1l,
    const bf16* __restrict__ w3h, const bf16* __restrict__ w3l,
    float* __restrict__ gate, float* __restrict__ up,
    const int* __restrict__ gidx)
{
    extern __shared__ char smc[];
    const int bx = blockIdx.x, by = blockIdx.y;
    const bool text = by >= 8, isup = bx >= 64;
    const bf16* Bh = text ? (isup ? w3h : w1h) : (isup ? v3h : v1h);
    const bf16* Bl = text ? (isup ? w3l : w1l) : (isup ? v3l : v1l);
    float* C = isup ? up : gate;
    gemm_core(Ahg, Alg, Bh, Bl, C, FF, HDIM, by * 128, (bx & 63) * 128,
              gidx, nullptr, nullptr, smc, nullptr, nullptr);
}

// ---------------- fused down-proj GEMM: grid (16, 16) ----------------
__global__ void __launch_bounds__(128, 2) down_kernel(
    const bf16* __restrict__ Ahg, const bf16* __restrict__ Alg,
    const bf16* __restrict__ v2h, const bf16* __restrict__ v2l,
    const bf16* __restrict__ w2h, const bf16* __restrict__ w2l,
    float* __restrict__ out, const int* __restrict__ gidx)
{
    extern __shared__ char smc[];
    const int by = blockIdx.y;
    const bool text = by >= 8;
    gemm_core(Ahg, Alg, text ? w2h : v2h, text ? w2l : v2l, out, HDIM, FF,
              by * 128, blockIdx.x * 128, nullptr, gidx, nullptr, smc, nullptr, nullptr);
}

// ---------------- RMSNorm (R9 scalar) -> bf16 hi/lo (+ optional fp32 copy) ----------------
__global__ void rmsnorm_kernel(const float* __restrict__ x, const float* __restrict__ w,
                               bf16* __restrict__ yh, bf16* __restrict__ yl,
                               float* __restrict__ yf) {
    int row = blockIdx.x;
    const float* xr = x + (size_t)row * HDIM;
    float ss = 0.f;
    for (int i = threadIdx.x; i < HDIM; i += 256) { float v = xr[i]; ss = fmaf(v, v, ss); }
    for (int o = 16; o > 0; o >>= 1) ss += __shfl_xor_sync(0xffffffffu, ss, o);
    __shared__ float red[8];
    int wid = threadIdx.x >> 5, lane = threadIdx.x & 31;
    if (lane == 0) red[wid] = ss;
    __syncthreads();
    if (wid == 0) {
        float t = (lane < 8) ? red[lane] : 0.f;
        for (int o = 4; o > 0; o >>= 1) t += __shfl_xor_sync(0xffffffffu, t, o);
        if (lane == 0) red[0] = t;
    }
    __syncthreads();
    float scale = rsqrtf(red[0] / (float)HDIM + 1e-6f);
    for (int i = threadIdx.x; i < HDIM; i += 256) {
        float v = xr[i] * scale * w[i];
        bf16 h = __float2bfloat16(v);
        yh[(size_t)row * HDIM + i] = h;
        yl[(size_t)row * HDIM + i] = __float2bfloat16(v - __bfloat162float(h));
        if (yf) yf[(size_t)row * HDIM + i] = v;
    }
}

// ---------------- RoPE + convert to bf16 hi/lo ----------------
__global__ void ropeconv_kernel(const float* __restrict__ q, const float* __restrict__ k,
                                const float* __restrict__ cosb, const float* __restrict__ sinb,
                                bf16* __restrict__ qh, bf16* __restrict__ ql,
                                bf16* __restrict__ kh, bf16* __restrict__ kl) {
    int idx = blockIdx.x * blockDim.x + threadIdx.x;
    if (idx >= SQ * 24 * 64) return;
    int d  = idx & 63;
    int hh = (idx >> 6) % 24;
    int s  = idx / (24 * 64);
    float c1 = cosb[s * HD + d],      s1 = sinb[s * HD + d];
    float c2 = cosb[s * HD + d + 64], s2 = sinb[s * HD + d + 64];
    size_t off;
    const float* src;
    bf16 *dh, *dl;
    if (hh < NH) {
        off = (size_t)s * (NH * HD) + hh * HD;
        src = q + off; dh = qh + off; dl = ql + off;
    } else {
        off = (size_t)s * (NKV * HD) + (hh - NH) * HD;
        src = k + off; dh = kh + off; dl = kl + off;
    }
    float a = src[d], b = src[d + 64];
    float r1 = a * c1 - b * s1;
    float r2 = b * c2 + a * s2;
    bf16 h1 = __float2bfloat16(r1), h2 = __float2bfloat16(r2);
    dh[d] = h1;      dl[d] = __float2bfloat16(r1 - __bfloat162float(h1));
    dh[d + 64] = h2; dl[d + 64] = __float2bfloat16(r2 - __bfloat162float(h2));
}

// ---------------- concat row-index kernel ----------------
__global__ void concat_idx_kernel(const int* __restrict__ vis, const int* __restrict__ txt,
                                  int* __restrict__ gidx) {
    int i = blockIdx.x * 256 + threadIdx.x;
    if (i < 1024) gidx[i] = vis[i];
    else if (i < 2048) gidx[i] = txt[i - 1024];
}

// ---------------- HMMA flash attention (causal, GQA rep=2) ----------------
#define FSTRIDE   272
#define FQ_BYTES  (128 * FSTRIDE)
#define FKV_BYTES (64 * FSTRIDE)
#define FLASH_SMEM (2 * FQ_BYTES + 8 * FKV_BYTES)

__global__ void __launch_bounds__(256, 1) flash_kernel(
    const bf16* __restrict__ qh, const bf16* __restrict__ ql,
    const bf16* __restrict__ kh, const bf16* __restrict__ kl,
    const bf16* __restrict__ vh, const bf16* __restrict__ vl,
    bf16* __restrict__ oh, bf16* __restrict__ ol)
{
    extern __shared__ char sm[];
    const uint32_t base = smem_to_u32(sm);
    const int h = blockIdx.y, kvh = h >> 1;
    const int qt = (gridDim.x - 1) - blockIdx.x;
    const int q0 = qt * 128;
    const int tid = threadIdx.x, lane = tid & 31, w = tid >> 5;

    const uint32_t Qh_s = base;
    const uint32_t KV0  = base + 2 * FQ_BYTES;

    for (int c = tid; c < 2048; c += 256) {
        int r = c >> 4, dd = (c & 15) * 8;
        size_t src = (size_t)(q0 + r) * (NH * HD) + h * HD + dd;
        uint32_t dst = Qh_s + r * FSTRIDE + dd * 2;
        cp_async16(dst, qh + src);
        cp_async16(dst + FQ_BYTES, ql + src);
    }
#define LOAD_KV(KB, BUF) do { \
    uint32_t s_ = KV0 + (BUF) * 4 * FKV_BYTES; \
    for (int c = tid; c < 1024; c += 256) { \
        int r_ = c >> 4, dd_ = (c & 15) * 8; \
        size_t src_ = (size_t)((KB) * 64 + r_) * (NKV * HD) + kvh * HD + dd_; \
        uint32_t dst_ = s_ + r_ * FSTRIDE + dd_ * 2; \
        cp_async16(dst_,                 kh + src_); \
        cp_async16(dst_ + FKV_BYTES,     kl + src_); \
        cp_async16(dst_ + 2 * FKV_BYTES, vh + src_); \
        cp_async16(dst_ + 3 * FKV_BYTES, vl + src_); \
    } } while (0)

    LOAD_KV(0, 0);
    CP_COMMIT();

    const int nkb = 2 * (qt + 1);
    const int g = lane >> 2, t = lane & 3;
    const int a_row = lane & 15, a_sel = (lane >> 4) * 8;
    const int b_row = lane & 7,  b_sel = ((lane >> 3) & 1) * 8;
    const int row0 = q0 + w * 16 + g;
    const int row1 = row0 + 8;
    const float scale = 0.08838834764831845f;

    float m0v = -1e30f, m1v = -1e30f, l0 = 0.f, l1 = 0.f;
    float acc[16][4];
#pragma unroll
    for (int i = 0; i < 16; i++)
#pragma unroll
        for (int j = 0; j < 4; j++) acc[i][j] = 0.f;

    for (int kb = 0; kb < nkb; kb++) {
        const int buf = kb & 1;
        if (kb + 1 < nkb) { LOAD_KV(kb + 1, buf ^ 1); CP_COMMIT(); CP_WAIT1(); }
        else CP_WAIT0();
        __syncthreads();
        const uint32_t Kh_s = KV0 + buf * 4 * FKV_BYTES;
        const uint32_t Kl_s = Kh_s + FKV_BYTES;
        const uint32_t Vh_s = Kh_s + 2 * FKV_BYTES;
        const uint32_t Vl_s = Kh_s + 3 * FKV_BYTES;

        float sc[8][4];
#pragma unroll
        for (int i = 0; i < 8; i++)
#pragma unroll
            for (int j = 0; j < 4; j++) sc[i][j] = 0.f;
#pragma unroll
        for (int ks = 0; ks < 8; ks++) {
            uint32_t aH[4], aL[4];
            uint32_t qaddr = Qh_s + (uint32_t)((w * 16 + a_row) * FSTRIDE + (ks * 16 + a_sel) * 2);
            ldmatrix_x4(aH, qaddr);
            ldmatrix_x4(aL, qaddr + FQ_BYTES);
#pragma unroll
            for (int ni = 0; ni < 8; ni++) {
                uint32_t bH[2], bL[2];
                uint32_t kaddr = Kh_s + (uint32_t)((ni * 8 + b_row) * FSTRIDE + (ks * 16 + b_sel) * 2);
                ldmatrix_x2(bH, kaddr);
                ldmatrix_x2(bL, kaddr + FKV_BYTES);
                mma_bf16(sc[ni], aH, bH);
                mma_bf16(sc[ni], aH, bL);
                mma_bf16(sc[ni], aL, bH);
            }
        }
        float mr0 = -1e30f, mr1 = -1e30f;
#pragma unroll
        for (int ni = 0; ni < 8; ni++) {
            int c0 = kb * 64 + ni * 8 + 2 * t, c1 = c0 + 1;
            sc[ni][0] = (c0 <= row0) ? sc[ni][0] * scale : -1e30f;
            sc[ni][1] = (c1 <= row0) ? sc[ni][1] * scale : -1e30f;
            sc[ni][2] = (c0 <= row1) ? sc[ni][2] * scale : -1e30f;
            sc[ni][3] = (c1 <= row1) ? sc[ni][3] * scale : -1e30f;
            mr0 = fmaxf(mr0, fmaxf(sc[ni][0], sc[ni][1]));
            mr1 = fmaxf(mr1, fmaxf(sc[ni][2], sc[ni][3]));
        }
        mr0 = fmaxf(mr0, __shfl_xor_sync(0xffffffffu, mr0, 1));
        mr0 = fmaxf(mr0, __shfl_xor_sync(0xffffffffu, mr0, 2));
        mr1 = fmaxf(mr1, __shfl_xor_sync(0xffffffffu, mr1, 1));
        mr1 = fmaxf(mr1, __shfl_xor_sync(0xffffffffu, mr1, 2));
        float mn0 = fmaxf(m0v, mr0), mn1 = fmaxf(m1v, mr1);
        float al0 = __expf(m0v - mn0), al1 = __expf(m1v - mn1);
        float ps0 = 0.f, ps1 = 0.f;
        uint32_t pH[4][4], pL[4][4];
#pragma unroll
        for (int ni = 0; ni < 8; ni++) {
            float p0 = __expf(sc[ni][0] - mn0), p1 = __expf(sc[ni][1] - mn0);
            float p2 = __expf(sc[ni][2] - mn1), p3 = __expf(sc[ni][3] - mn1);
            ps0 += p0 + p1; ps1 += p2 + p3;
            int ks = ni >> 1, hf = ni & 1;
            bf16 b0 = __float2bfloat16(p0), b1 = __float2bfloat16(p1);
            bf16 b2 = __float2bfloat16(p2), b3 = __float2bfloat16(p3);
            pH[ks][hf * 2 + 0] = ((uint32_t)__bfloat16_as_ushort(b1) << 16) | __bfloat16_as_ushort(b0);
            pH[ks][hf * 2 + 1] = ((uint32_t)__bfloat16_as_ushort(b3) << 16) | __bfloat16_as_ushort(b2);
            pL[ks][hf * 2 + 0] = pack2bf(p0 - __bfloat162float(b0), p1 - __bfloat162float(b1));
            pL[ks][hf * 2 + 1] = pack2bf(p2 - __bfloat162float(b2), p3 - __bfloat162float(b3));
        }
        ps0 += __shfl_xor_sync(0xffffffffu, ps0, 1);
        ps0 += __shfl_xor_sync(0xffffffffu, ps0, 2);
        ps1 += __shfl_xor_sync(0xffffffffu, ps1, 1);
        ps1 += __shfl_xor_sync(0xffffffffu, ps1, 2);
        l0 = l0 * al0 + ps0; l1 = l1 * al1 + ps1;
        m0v = mn0; m1v = mn1;
#pragma unroll
        for (int dj = 0; dj < 16; dj++) {
            acc[dj][0] *= al0; acc[dj][1] *= al0;
            acc[dj][2] *= al1; acc[dj][3] *= al1;
        }
#pragma unroll
        for (int ks = 0; ks < 4; ks++) {
#pragma unroll
            for (int dj = 0; dj < 16; dj++) {
                uint32_t bH[2], bL[2];
                uint32_t vaddr = Vh_s + (uint32_t)((ks * 16 + (lane & 15)) * FSTRIDE + dj * 16);
                ldmatrix_x2_trans(bH, vaddr);
                ldmatrix_x2_trans(bL, vaddr + FKV_BYTES);
                mma_bf16(acc[dj], pH[ks], bH);
                mma_bf16(acc[dj], pH[ks], bL);
                mma_bf16(acc[dj], pL[ks], bH);
            }
        }
        __syncthreads();
    }

    float inv0 = 1.f / l0, inv1 = 1.f / l1;
#pragma unroll
    for (int dj = 0; dj < 16; dj++) {
        int col = h * HD + dj * 8 + 2 * t;
        {
            float v0 = acc[dj][0] * inv0, v1 = acc[dj][1] * inv0;
            bf16 h0 = __float2bfloat16(v0), h1b = __float2bfloat16(v1);
            size_t o = (size_t)row0 * HDIM + col;
            *(uint32_t*)(oh + o) = ((uint32_t)__bfloat16_as_ushort(h1b) << 16) | __bfloat16_as_ushort(h0);
            *(uint32_t*)(ol + o) = pack2bf(v0 - __bfloat162float(h0), v1 - __bfloat162float(h1b));
        }
        {
            float v0 = acc[dj][2] * inv1, v1 = acc[dj][3] * inv1;
            bf16 h0 = __float2bfloat16(v0), h1b = __float2bfloat16(v1);
            size_t o = (size_t)row1 * HDIM + col;
            *(uint32_t*)(oh + o) = ((uint32_t)__bfloat16_as_ushort(h1b) << 16) | __bfloat16_as_ushort(h0);
            *(uint32_t*)(ol + o) = pack2bf(v0 - __bfloat162float(h0), v1 - __bfloat162float(h1b));
        }
    }
#undef LOAD_KV
}

// ---------------- SiLU(gate)*up -> bf16 hi/lo ----------------
__global__ void silu_mul_kernel(const float* __restrict__ gf, const float* __restrict__ uf,
                                bf16* __restrict__ gh, bf16* __restrict__ gl, int n4) {
    int i = blockIdx.x * blockDim.x + threadIdx.x;
    if (i >= n4) return;
    float4 a = ((const float4*)gf)[i];
    float4 b = ((const float4*)uf)[i];
    float r[4];
    r[0] = a.x / (1.f + __expf(-a.x)) * b.x;
    r[1] = a.y / (1.f + __expf(-a.y)) * b.y;
    r[2] = a.z / (1.f + __expf(-a.z)) * b.z;
    r[3] = a.w / (1.f + __expf(-a.w)) * b.w;
#pragma unroll
    for (int j = 0; j < 4; j++) {
        bf16 h = __float2bfloat16(r[j]);
        gh[i * 4 + j] = h;
        gl[i * 4 + j] = __float2bfloat16(r[j] - __bfloat162float(h));
    }
}

// ---------------- launch ----------------
extern "C" void kernel_launch(void* const* d_in, const int* in_sizes, int n_in,
                              void* d_out, int out_size) {
    const float* x    = (const float*)d_in[0];
    const float* cosb = (const float*)d_in[1];
    const float* sinb = (const float*)d_in[2];
    const float* wq   = (const float*)d_in[3];
    const float* wk   = (const float*)d_in[4];
    const float* wv   = (const float*)d_in[5];
    const float* wo   = (const float*)d_in[6];
    const float* w1   = (const float*)d_in[7];
    const float* w3   = (const float*)d_in[8];
    const float* w2   = (const float*)d_in[9];
    const float* v1   = (const float*)d_in[10];
    const float* v3   = (const float*)d_in[11];
    const float* v2   = (const float*)d_in[12];
    const float* anw  = (const float*)d_in[13];
    const float* fnw  = (const float*)d_in[14];
    const int*   vis  = (const int*)d_in[15];
    const int*   txt  = (const int*)d_in[16];

    float* out = (float*)d_out;
    float* res = out + (size_t)SQ * HDIM;

#define SYM(p, s) void* p##_; cudaGetSymbolAddress(&p##_, s);
    SYM(qf, g_qf) SYM(kf, g_kf) SYM(gate2, g_gate2) SYM(up2, g_up2)
    SYM(h1h, g_h1h) SYM(h1l, g_h1l) SYM(oh, g_oh) SYM(ol, g_ol) SYM(gh2, g_gh2) SYM(gl2, g_gl2)
    SYM(gidx, g_gidx)
    SYM(qh, g_qh) SYM(ql, g_ql) SYM(kh, g_kh) SYM(kl, g_kl) SYM(vh, g_vh) SYM(vl, g_vl)
    SYM(wqh, g_wqh) SYM(wql, g_wql) SYM(wkh, g_wkh) SYM(wkl, g_wkl)
    SYM(wvh, g_wvh) SYM(wvl, g_wvl) SYM(woh, g_woh) SYM(wol, g_wol)
    SYM(w1h, g_w1h) SYM(w1l, g_w1l) SYM(w3h, g_w3h) SYM(w3l, g_w3l)
    SYM(v1h, g_v1h) SYM(v1l, g_v1l) SYM(v3h, g_v3h) SYM(v3l, g_v3l)
    SYM(w2h, g_w2h) SYM(w2l, g_w2l) SYM(v2h, g_v2h) SYM(v2l, g_v2l)
#undef SYM

    cudaFuncSetAttribute(flash_kernel, cudaFuncAttributeMaxDynamicSharedMemorySize, FLASH_SMEM);
    cudaFuncSetAttribute(tgemm_kernel, cudaFuncAttributeMaxDynamicSharedMemorySize, GSMEM);
    cudaFuncSetAttribute(qkv_kernel,   cudaFuncAttributeMaxDynamicSharedMemorySize, GSMEM);
    cudaFuncSetAttribute(ffn_kernel,   cudaFuncAttributeMaxDynamicSharedMemorySize, GSMEM);
    cudaFuncSetAttribute(down_kernel,  cudaFuncAttributeMaxDynamicSharedMemorySize, GSMEM);

    // side stream + events (host-side objects only, created once)
    static cudaStream_t s2 = nullptr;
    static cudaEvent_t evFork = nullptr, evJoin1 = nullptr, evJoin2 = nullptr;
    if (s2 == nullptr) {
        cudaStreamCreateWithFlags(&s2, cudaStreamNonBlocking);
        cudaEventCreateWithFlags(&evFork, cudaEventDisableTiming);
        cudaEventCreateWithFlags(&evJoin1, cudaEventDisableTiming);
        cudaEventCreateWithFlags(&evJoin2, cudaEventDisableTiming);
    }

    // ---- fork all converts onto s2; rmsnorm runs concurrently on main ----
    cudaEventRecord(evFork, 0);
    cudaStreamWaitEvent(s2, evFork, 0);
    concat_idx_kernel<<<8, 256, 0, s2>>>(vis, txt, (int*)gidx_);
    wconvert_kernel<<<dim3(HDIM / 64, HDIM / 64), 256, 0, s2>>>(wq, (bf16*)wqh_, (bf16*)wql_, HDIM, HDIM);
    wconvert_kernel<<<dim3(1024 / 64, HDIM / 64), 256, 0, s2>>>(wk, (bf16*)wkh_, (bf16*)wkl_, HDIM, 1024);
    wconvert_kernel<<<dim3(1024 / 64, HDIM / 64), 256, 0, s2>>>(wv, (bf16*)wvh_, (bf16*)wvl_, HDIM, 1024);
    cudaEventRecord(evJoin1, s2);
    wconvert_kernel<<<dim3(HDIM / 64, HDIM / 64), 256, 0, s2>>>(wo, (bf16*)woh_, (bf16*)wol_, HDIM, HDIM);
    wconvert_kernel<<<dim3(FF / 64, HDIM / 64), 256, 0, s2>>>(w1, (bf16*)w1h_, (bf16*)w1l_, HDIM, FF);
    wconvert_kernel<<<dim3(FF / 64, HDIM / 64), 256, 0, s2>>>(w3, (bf16*)w3h_, (bf16*)w3l_, HDIM, FF);
    wconvert_kernel<<<dim3(FF / 64, HDIM / 64), 256, 0, s2>>>(v1, (bf16*)v1h_, (bf16*)v1l_, HDIM, FF);
    wconvert_kernel<<<dim3(FF / 64, HDIM / 64), 256, 0, s2>>>(v3, (bf16*)v3h_, (bf16*)v3l_, HDIM, FF);
    wconvert_kernel<<<dim3(HDIM / 64, FF / 64), 256, 0, s2>>>(w2, (bf16*)w2h_, (bf16*)w2l_, FF, HDIM);
    wconvert_kernel<<<dim3(HDIM / 64, FF / 64), 256, 0, s2>>>(v2, (bf16*)v2h_, (bf16*)v2l_, FF, HDIM);
    cudaEventRecord(evJoin2, s2);

    // ---- main stream ----
    // 1) attn rmsnorm -> bf16 hi/lo (concurrent with wq/wk/wv converts)
    rmsnorm_kernel<<<SQ, 256>>>(x, anw, (bf16*)h1h_, (bf16*)h1l_, nullptr);
    // join1: qkv needs wq/wk/wv
    cudaStreamWaitEvent(0, evJoin1, 0);
    // 2) QKV projections (fused; V writes bf16 hi/lo directly)
    qkv_kernel<<<dim3(32, SQ / 128), 128, GSMEM>>>((bf16*)h1h_, (bf16*)h1l_,
        (bf16*)wqh_, (bf16*)wql_, (bf16*)wkh_, (bf16*)wkl_, (bf16*)wvh_, (bf16*)wvl_,
        (float*)qf_, (float*)kf_, (bf16*)vh_, (bf16*)vl_);
    // 3) RoPE + convert q,k
    {
        int n = SQ * 24 * 64;
        ropeconv_kernel<<<(n + 255) / 256, 256>>>((float*)qf_, (float*)kf_, cosb, sinb,
            (bf16*)qh_, (bf16*)ql_, (bf16*)kh_, (bf16*)kl_);
    }
    // 4) attention (HMMA flash)
    flash_kernel<<<dim3(SQ / 128, NH), 256, FLASH_SMEM>>>((bf16*)qh_, (bf16*)ql_, (bf16*)kh_, (bf16*)kl_,
        (bf16*)vh_, (bf16*)vl_, (bf16*)oh_, (bf16*)ol_);
    // join2: wo/FF weights
    cudaStreamWaitEvent(0, evJoin2, 0);
    // 5) o-proj + residual -> res
    tgemm_kernel<<<dim3(HDIM / 128, SQ / 128), 128, GSMEM>>>((bf16*)oh_, (bf16*)ol_, (bf16*)woh_, (bf16*)wol_,
        res, HDIM, HDIM, nullptr, nullptr, x);
    // 6) ffn rmsnorm -> bf16 hi/lo + fp32 baseline into out
    rmsnorm_kernel<<<SQ, 256>>>(res, fnw, (bf16*)h1h_, (bf16*)h1l_, out);
    // 7) all four FF GEMMs fused (vision+text, gate+up)
    ffn_kernel<<<dim3(128, 16), 128, GSMEM>>>((bf16*)h1h_, (bf16*)h1l_,
        (bf16*)v1h_, (bf16*)v1l_, (bf16*)v3h_, (bf16*)v3l_,
        (bf16*)w1h_, (bf16*)w1l_, (bf16*)w3h_, (bf16*)w3l_,
        (float*)gate2_, (float*)up2_, (int*)gidx_);
    // 8) fused silu over both branches
    silu_mul_kernel<<<(2048 * FF / 4 + 255) / 256, 256>>>((float*)gate2_, (float*)up2_,
        (bf16*)gh2_, (bf16*)gl2_, 2048 * FF / 4);
    // 9) fused down-proj (w2 + v2), scatter to out
    down_kernel<<<dim3(16, 16), 128, GSMEM>>>((bf16*)gh2_, (bf16*)gl2_,
        (bf16*)v2h_, (bf16*)v2l_, (bf16*)w2h_, (bf16*)w2l_, out, (int*)gidx_);
}

// round 16
// speedup vs baseline: 1.0382x; 1.0382x over previous
#include <cuda_runtime.h>
#include <cuda_bf16.h>
#include <cstdint>
#include <math.h>

#define SQ   2048
#define HDIM 2048
#define NH   16
#define NKV  8
#define HD   128
#define FF   8192

typedef __nv_bfloat16 bf16;

// ---------------- scratch (device globals; no allocs allowed) ----------------
__device__ float g_qf[SQ * NH * HD];
__device__ float g_kf[SQ * NKV * HD];
__device__ float g_gate2[2048 * FF];
__device__ float g_up2[2048 * FF];

__device__ bf16 g_h1h[SQ * HDIM],  g_h1l[SQ * HDIM];
__device__ bf16 g_oh[SQ * HDIM],   g_ol[SQ * HDIM];
__device__ bf16 g_gh2[2048 * FF],  g_gl2[2048 * FF];
__device__ int  g_gidx[2048];

__device__ bf16 g_qh[SQ * NH * HD],  g_ql[SQ * NH * HD];
__device__ bf16 g_kh[SQ * NKV * HD], g_kl[SQ * NKV * HD];
__device__ bf16 g_vh[SQ * NKV * HD], g_vl[SQ * NKV * HD];

// transposed weights [N][K], hi/lo
__device__ bf16 g_wqh[HDIM * HDIM], g_wql[HDIM * HDIM];
__device__ bf16 g_wkh[1024 * HDIM], g_wkl[1024 * HDIM];
__device__ bf16 g_wvh[1024 * HDIM], g_wvl[1024 * HDIM];
__device__ bf16 g_woh[HDIM * HDIM], g_wol[HDIM * HDIM];
__device__ bf16 g_w1h[FF * HDIM],   g_w1l[FF * HDIM];
__device__ bf16 g_w3h[FF * HDIM],   g_w3l[FF * HDIM];
__device__ bf16 g_v1h[FF * HDIM],   g_v1l[FF * HDIM];
__device__ bf16 g_v3h[FF * HDIM],   g_v3l[FF * HDIM];
__device__ bf16 g_w2h[HDIM * FF],   g_w2l[HDIM * FF];
__device__ bf16 g_v2h[HDIM * FF],   g_v2l[HDIM * FF];

// ---------------- helpers ----------------
__device__ __forceinline__ uint32_t smem_to_u32(const void* p) {
    uint32_t a;
    asm("{ .reg .u64 t; cvta.to.shared.u64 t, %1; cvt.u32.u64 %0, t; }" : "=r"(a) : "l"(p));
    return a;
}
__device__ __forceinline__ void ldmatrix_x4(uint32_t* r, uint32_t addr) {
    asm volatile("ldmatrix.sync.aligned.m8n8.x4.shared.b16 {%0,%1,%2,%3}, [%4];"
        : "=r"(r[0]), "=r"(r[1]), "=r"(r[2]), "=r"(r[3]) : "r"(addr));
}
__device__ __forceinline__ void ldmatrix_x2(uint32_t* r, uint32_t addr) {
    asm volatile("ldmatrix.sync.aligned.m8n8.x2.shared.b16 {%0,%1}, [%2];"
        : "=r"(r[0]), "=r"(r[1]) : "r"(addr));
}
__device__ __forceinline__ void ldmatrix_x2_trans(uint32_t* r, uint32_t addr) {
    asm volatile("ldmatrix.sync.aligned.m8n8.x2.trans.shared.b16 {%0,%1}, [%2];"
        : "=r"(r[0]), "=r"(r[1]) : "r"(addr));
}
__device__ __forceinline__ void mma_bf16(float* c, const uint32_t* a, const uint32_t* b) {
    asm volatile(
        "mma.sync.aligned.m16n8k16.row.col.f32.bf16.bf16.f32 "
        "{%0,%1,%2,%3}, {%4,%5,%6,%7}, {%8,%9}, {%0,%1,%2,%3};"
        : "+f"(c[0]), "+f"(c[1]), "+f"(c[2]), "+f"(c[3])
        : "r"(a[0]), "r"(a[1]), "r"(a[2]), "r"(a[3]), "r"(b[0]), "r"(b[1]));
}
__device__ __forceinline__ void cp_async16(uint32_t dst, const void* src) {
    asm volatile("cp.async.cg.shared.global [%0], [%1], 16;" :: "r"(dst), "l"(src));
}
#define CP_COMMIT() asm volatile("cp.async.commit_group;" ::: "memory")
#define CP_WAIT1()  asm volatile("cp.async.wait_group 1;" ::: "memory")
#define CP_WAIT0()  asm volatile("cp.async.wait_group 0;" ::: "memory")

__device__ __forceinline__ uint32_t pack2bf(float x, float y) {
    __nv_bfloat16 bx = __float2bfloat16(x), by = __float2bfloat16(y);
    return ((uint32_t)__bfloat16_as_ushort(by) << 16) | (uint32_t)__bfloat16_as_ushort(bx);
}

// ---------------- weight convert (R9): W[K][N] fp32 -> th,tl [N][K] bf16 ----------------
__global__ void __launch_bounds__(256) wconvert_kernel(
    const float* __restrict__ W, bf16* __restrict__ th,
    bf16* __restrict__ tl, int Kd, int Nd) {
    __shared__ float t[64][65];
    const int kb = blockIdx.y * 64, nb = blockIdx.x * 64;
    const int tx = threadIdx.x & 15, ty = threadIdx.x >> 4;
#pragma unroll
    for (int i = 0; i < 4; i++) {
        int r = ty + i * 16;
        float4 v = *(const float4*)&W[(size_t)(kb + r) * Nd + nb + tx * 4];
        t[r][tx * 4 + 0] = v.x;
        t[r][tx * 4 + 1] = v.y;
        t[r][tx * 4 + 2] = v.z;
        t[r][tx * 4 + 3] = v.w;
    }
    __syncthreads();
    const int n = threadIdx.x >> 2, kc = (threadIdx.x & 3) * 16;
    uint32_t hv[8], lv[8];
#pragma unroll
    for (int j = 0; j < 8; j++) {
        float a = t[kc + 2 * j][n], b = t[kc + 2 * j + 1][n];
        bf16 ha = __float2bfloat16(a), hb = __float2bfloat16(b);
        hv[j] = ((uint32_t)__bfloat16_as_ushort(hb) << 16) | __bfloat16_as_ushort(ha);
        lv[j] = pack2bf(a - __bfloat162float(ha), b - __bfloat162float(hb));
    }
    size_t o = (size_t)(nb + n) * Kd + kb + kc;
    *(uint4*)(th + o)     = make_uint4(hv[0], hv[1], hv[2], hv[3]);
    *(uint4*)(th + o + 8) = make_uint4(hv[4], hv[5], hv[6], hv[7]);
    *(uint4*)(tl + o)     = make_uint4(lv[0], lv[1], lv[2], lv[3]);
    *(uint4*)(tl + o + 8) = make_uint4(lv[4], lv[5], lv[6], lv[7]);
}

// ---------------- GEMM core (R14): 128 threads, 4 warps (2x2), warp tile 64x64 ----------------
#define PAB   80
#define ARR   10240
#define STAGE 40960
#define GSMEM (2 * STAGE + 1024)

__device__ __forceinline__ void gemm_core(
    const bf16* __restrict__ Ahg, const bf16* __restrict__ Alg,
    const bf16* __restrict__ Bhg, const bf16* __restrict__ Blg,
    float* __restrict__ C, int N, int K, int m0, int n0,
    const int* __restrict__ arow, const int* __restrict__ crow,
    const float* __restrict__ cadd, char* smc,
    bf16* __restrict__ Chh, bf16* __restrict__ Cll)
{
    const uint32_t base = smem_to_u32(smc);
    int* rowA = (int*)(smc + 2 * STAGE);
    int* rowC = (int*)(smc + 2 * STAGE + 512);
    const int tid = threadIdx.x, lane = tid & 31, wid = tid >> 5;
    const int wm = wid & 1, wn = wid >> 1;

    rowA[tid] = arow ? arow[m0 + tid] : (m0 + tid);
    rowC[tid] = crow ? crow[m0 + tid] : (m0 + tid);
    __syncthreads();

    float acc[4][8][4];
#pragma unroll
    for (int i = 0; i < 4; i++)
#pragma unroll
        for (int j = 0; j < 8; j++)
#pragma unroll
            for (int q = 0; q < 4; q++) acc[i][j][q] = 0.f;

    const int a_row = lane & 15, a_sel = (lane >> 4) * 8;
    const int b4_row = (lane & 7) + ((lane >> 4) << 3);
    const int b4_sel = ((lane >> 3) & 1) * 8;
    const int niter = K >> 5;

#define LOAD_STAGE(IT, B) do { \
    int k0_ = (IT) * 32; \
    uint32_t s_ = base + (B) * STAGE; \
    _Pragma("unroll") \
    for (int c = tid; c < 512; c += 128) { \
        int row_ = c >> 2, ko_ = (c & 3) << 3; \
        size_t asrc_ = (size_t)rowA[row_] * K + k0_ + ko_; \
        size_t bsrc_ = (size_t)(n0 + row_) * K + k0_ + ko_; \
        uint32_t d_ = s_ + row_ * PAB + ko_ * 2; \
        cp_async16(d_,           Ahg + asrc_); \
        cp_async16(d_ + ARR,     Alg + asrc_); \
        cp_async16(d_ + 2 * ARR, Bhg + bsrc_); \
        cp_async16(d_ + 3 * ARR, Blg + bsrc_); \
    } } while (0)

    LOAD_STAGE(0, 0);
    CP_COMMIT();

    for (int it = 0; it < niter; it++) {
        const int b = it & 1;
        if (it + 1 < niter) LOAD_STAGE(it + 1, b ^ 1);
        CP_COMMIT();
        CP_WAIT1();
        __syncthreads();
        const uint32_t Ah_s = base + b * STAGE, Al_s = Ah_s + ARR;
        const uint32_t Bh_s = Ah_s + 2 * ARR,   Bl_s = Ah_s + 3 * ARR;
#pragma unroll
        for (int ks = 0; ks < 2; ks++) {
            uint32_t aH[4][4], aL[4][4];
#pragma unroll
            for (int mi = 0; mi < 4; mi++) {
                int row = wm * 64 + mi * 16 + a_row;
                uint32_t byte = (uint32_t)(row * PAB + (ks * 16 + a_sel) * 2);
                ldmatrix_x4(aH[mi], Ah_s + byte);
                ldmatrix_x4(aL[mi], Al_s + byte);
            }
#pragma unroll
            for (int nip = 0; nip < 4; nip++) {
                uint32_t bH[4], bL[4];
                int row = wn * 64 + nip * 16 + b4_row;
                uint32_t byte = (uint32_t)(row * PAB + (ks * 16 + b4_sel) * 2);
                ldmatrix_x4(bH, Bh_s + byte);
                ldmatrix_x4(bL, Bl_s + byte);
#pragma unroll
                for (int mi = 0; mi < 4; mi++) {
                    mma_bf16(acc[mi][nip * 2 + 0], aH[mi], bH + 0);
                    mma_bf16(acc[mi][nip * 2 + 0], aH[mi], bL + 0);
                    mma_bf16(acc[mi][nip * 2 + 0], aL[mi], bH + 0);
                    mma_bf16(acc[mi][nip * 2 + 1], aH[mi], bH + 2);
                    mma_bf16(acc[mi][nip * 2 + 1], aH[mi], bL + 2);
                    mma_bf16(acc[mi][nip * 2 + 1], aL[mi], bH + 2);
                }
            }
        }
        __syncthreads();
    }
#undef LOAD_STAGE

    const int g = lane >> 2, t = lane & 3;
#pragma unroll
    for (int mi = 0; mi < 4; mi++) {
#pragma unroll
        for (int half = 0; half < 2; half++) {
            int rl = wm * 64 + mi * 16 + g + half * 8;
            int orow = rowC[rl];
            if (Chh) {
                bf16* Hp = Chh + (size_t)orow * N + n0;
                bf16* Lp = Cll + (size_t)orow * N + n0;
#pragma unroll
                for (int ni = 0; ni < 8; ni++) {
                    int col = wn * 64 + ni * 8 + t * 2;
                    float v0 = acc[mi][ni][half * 2 + 0];
                    float v1 = acc[mi][ni][half * 2 + 1];
                    bf16 h0 = __float2bfloat16(v0), h1 = __float2bfloat16(v1);
                    *(uint32_t*)(Hp + col) = ((uint32_t)__bfloat16_as_ushort(h1) << 16) | __bfloat16_as_ushort(h0);
                    *(uint32_t*)(Lp + col) = pack2bf(v0 - __bfloat162float(h0), v1 - __bfloat162float(h1));
                }
            } else {
                float* Cp = C + (size_t)orow * N + n0;
                const float* ap = cadd ? (cadd + (size_t)(m0 + rl) * N + n0) : nullptr;
#pragma unroll
                for (int ni = 0; ni < 8; ni++) {
                    int col = wn * 64 + ni * 8 + t * 2;
                    float2 v;
                    v.x = acc[mi][ni][half * 2 + 0];
                    v.y = acc[mi][ni][half * 2 + 1];
                    if (ap) { v.x += ap[col]; v.y += ap[col + 1]; }
                    *(float2*)(Cp + col) = v;
                }
            }
        }
    }
}

// ---------------- generic GEMM (used for WO) ----------------
__global__ void __launch_bounds__(128, 2) tgemm_kernel(
    const bf16* __restrict__ Ahg, const bf16* __restrict__ Alg,
    const bf16* __restrict__ Bhg, const bf16* __restrict__ Blg,
    float* __restrict__ C, int N, int K,
    const int* __restrict__ arow, const int* __restrict__ crow,
    const float* __restrict__ cadd)
{
    extern __shared__ char smc[];
    gemm_core(Ahg, Alg, Bhg, Blg, C, N, K, blockIdx.y * 128, blockIdx.x * 128,
              arow, crow, cadd, smc, nullptr, nullptr);
}

// ---------------- fused QKV GEMM: grid (32, 16); V writes bf16 hi/lo directly ----------------
__global__ void __launch_bounds__(128, 2) qkv_kernel(
    const bf16* __restrict__ Ahg, const bf16* __restrict__ Alg,
    const bf16* __restrict__ wqh, const bf16* __restrict__ wql,
    const bf16* __restrict__ wkh, const bf16* __restrict__ wkl,
    const bf16* __restrict__ wvh, const bf16* __restrict__ wvl,
    float* __restrict__ qf, float* __restrict__ kf,
    bf16* __restrict__ vh, bf16* __restrict__ vl)
{
    extern __shared__ char smc[];
    const int bx = blockIdx.x;
    if (bx < 16) {
        gemm_core(Ahg, Alg, wqh, wql, qf, 2048, HDIM, blockIdx.y * 128, bx * 128,
                  nullptr, nullptr, nullptr, smc, nullptr, nullptr);
    } else if (bx < 24) {
        gemm_core(Ahg, Alg, wkh, wkl, kf, 1024, HDIM, blockIdx.y * 128, (bx - 16) * 128,
                  nullptr, nullptr, nullptr, smc, nullptr, nullptr);
    } else {
        gemm_core(Ahg, Alg, wvh, wvl, nullptr, 1024, HDIM, blockIdx.y * 128, (bx - 24) * 128,
                  nullptr, nullptr, nullptr, smc, vh, vl);
    }
}

// ---------------- fused FFN gate/up GEMM: grid (128, 16) ----------------
__global__ void __launch_bounds__(128, 2) ffn_kernel(
    const bf16* __restrict__ Ahg, const bf16* __restrict__ Alg,
    const bf16* __restrict__ v1h, const bf16* __restrict__ v1l,
    const bf16* __restrict__ v3h, const bf16* __restrict__ v3l,
    const bf16* __restrict__ w1h, const bf16* __restrict__ w1l,
    const bf16* __restrict__ w3h, const bf16* __restrict__ w3l,
    float* __restrict__ gate, float* __restrict__ up,
    const int* __restrict__ gidx)
{
    extern __shared__ char smc[];
    const int bx = blockIdx.x, by = blockIdx.y;
    const bool text = by >= 8, isup = bx >= 64;
    const bf16* Bh = text ? (isup ? w3h : w1h) : (isup ? v3h : v1h);
    const bf16* Bl = text ? (isup ? w3l : w1l) : (isup ? v3l : v1l);
    float* C = isup ? up : gate;
    gemm_core(Ahg, Alg, Bh, Bl, C, FF, HDIM, by * 128, (bx & 63) * 128,
              gidx, nullptr, nullptr, smc, nullptr, nullptr);
}

// ---------------- fused down-proj GEMM: grid (16, 16) ----------------
__global__ void __launch_bounds__(128, 2) down_kernel(
    const bf16* __restrict__ Ahg, const bf16* __restrict__ Alg,
    const bf16* __restrict__ v2h, const bf16* __restrict__ v2l,
    const bf16* __restrict__ w2h, const bf16* __restrict__ w2l,
    float* __restrict__ out, const int* __restrict__ gidx)
{
    extern __shared__ char smc[];
    const int by = blockIdx.y;
    const bool text = by >= 8;
    gemm_core(Ahg, Alg, text ? w2h : v2h, text ? w2l : v2l, out, HDIM, FF,
              by * 128, blockIdx.x * 128, nullptr, gidx, nullptr, smc, nullptr, nullptr);
}

// ---------------- RMSNorm (R9 scalar) -> bf16 hi/lo (+ optional fp32 copy) ----------------
__global__ void rmsnorm_kernel(const float* __restrict__ x, const float* __restrict__ w,
                               bf16* __restrict__ yh, bf16* __restrict__ yl,
                               float* __restrict__ yf) {
    int row = blockIdx.x;
    const float* xr = x + (size_t)row * HDIM;
    float ss = 0.f;
    for (int i = threadIdx.x; i < HDIM; i += 256) { float v = xr[i]; ss = fmaf(v, v, ss); }
    for (int o = 16; o > 0; o >>= 1) ss += __shfl_xor_sync(0xffffffffu, ss, o);
    __shared__ float red[8];
    int wid = threadIdx.x >> 5, lane = threadIdx.x & 31;
    if (lane == 0) red[wid] = ss;
    __syncthreads();
    if (wid == 0) {
        float t = (lane < 8) ? red[lane] : 0.f;
        for (int o = 4; o > 0; o >>= 1) t += __shfl_xor_sync(0xffffffffu, t, o);
        if (lane == 0) red[0] = t;
    }
    __syncthreads();
    float scale = rsqrtf(red[0] / (float)HDIM + 1e-6f);
    for (int i = threadIdx.x; i < HDIM; i += 256) {
        float v = xr[i] * scale * w[i];
        bf16 h = __float2bfloat16(v);
        yh[(size_t)row * HDIM + i] = h;
        yl[(size_t)row * HDIM + i] = __float2bfloat16(v - __bfloat162float(h));
        if (yf) yf[(size_t)row * HDIM + i] = v;
    }
}

// ---------------- RoPE + convert to bf16 hi/lo ----------------
__global__ void ropeconv_kernel(const float* __restrict__ q, const float* __restrict__ k,
                                const float* __restrict__ cosb, const float* __restrict__ sinb,
                                bf16* __restrict__ qh, bf16* __restrict__ ql,
                                bf16* __restrict__ kh, bf16* __restrict__ kl) {
    int idx = blockIdx.x * blockDim.x + threadIdx.x;
    if (idx >= SQ * 24 * 64) return;
    int d  = idx & 63;
    int hh = (idx >> 6) % 24;
    int s  = idx / (24 * 64);
    float c1 = cosb[s * HD + d],      s1 = sinb[s * HD + d];
    float c2 = cosb[s * HD + d + 64], s2 = sinb[s * HD + d + 64];
    size_t off;
    const float* src;
    bf16 *dh, *dl;
    if (hh < NH) {
        off = (size_t)s * (NH * HD) + hh * HD;
        src = q + off; dh = qh + off; dl = ql + off;
    } else {
        off = (size_t)s * (NKV * HD) + (hh - NH) * HD;
        src = k + off; dh = kh + off; dl = kl + off;
    }
    float a = src[d], b = src[d + 64];
    float r1 = a * c1 - b * s1;
    float r2 = b * c2 + a * s2;
    bf16 h1 = __float2bfloat16(r1), h2 = __float2bfloat16(r2);
    dh[d] = h1;      dl[d] = __float2bfloat16(r1 - __bfloat162float(h1));
    dh[d + 64] = h2; dl[d + 64] = __float2bfloat16(r2 - __bfloat162float(h2));
}

// ---------------- concat row-index kernel ----------------
__global__ void concat_idx_kernel(const int* __restrict__ vis, const int* __restrict__ txt,
                                  int* __restrict__ gidx) {
    int i = blockIdx.x * 256 + threadIdx.x;
    if (i < 1024) gidx[i] = vis[i];
    else if (i < 2048) gidx[i] = txt[i - 1024];
}

// ---------------- HMMA flash attention (causal, GQA rep=2) ----------------
#define FSTRIDE   272
#define FQ_BYTES  (128 * FSTRIDE)
#define FKV_BYTES (64 * FSTRIDE)
#define FLASH_SMEM (2 * FQ_BYTES + 8 * FKV_BYTES)

__global__ void __launch_bounds__(256, 1) flash_kernel(
    const bf16* __restrict__ qh, const bf16* __restrict__ ql,
    const bf16* __restrict__ kh, const bf16* __restrict__ kl,
    const bf16* __restrict__ vh, const bf16* __restrict__ vl,
    bf16* __restrict__ oh, bf16* __restrict__ ol)
{
    extern __shared__ char sm[];
    const uint32_t base = smem_to_u32(sm);
    const int h = blockIdx.y, kvh = h >> 1;
    const int qt = (gridDim.x - 1) - blockIdx.x;
    const int q0 = qt * 128;
    const int tid = threadIdx.x, lane = tid & 31, w = tid >> 5;

    const uint32_t Qh_s = base;
    const uint32_t KV0  = base + 2 * FQ_BYTES;

    for (int c = tid; c < 2048; c += 256) {
        int r = c >> 4, dd = (c & 15) * 8;
        size_t src = (size_t)(q0 + r) * (NH * HD) + h * HD + dd;
        uint32_t dst = Qh_s + r * FSTRIDE + dd * 2;
        cp_async16(dst, qh + src);
        cp_async16(dst + FQ_BYTES, ql + src);
    }
#define LOAD_KV(KB, BUF) do { \
    uint32_t s_ = KV0 + (BUF) * 4 * FKV_BYTES; \
    for (int c = tid; c < 1024; c += 256) { \
        int r_ = c >> 4, dd_ = (c & 15) * 8; \
        size_t src_ = (size_t)((KB) * 64 + r_) * (NKV * HD) + kvh * HD + dd_; \
        uint32_t dst_ = s_ + r_ * FSTRIDE + dd_ * 2; \
        cp_async16(dst_,                 kh + src_); \
        cp_async16(dst_ + FKV_BYTES,     kl + src_); \
        cp_async16(dst_ + 2 * FKV_BYTES, vh + src_); \
        cp_async16(dst_ + 3 * FKV_BYTES, vl + src_); \
    } } while (0)

    LOAD_KV(0, 0);
    CP_COMMIT();

    const int nkb = 2 * (qt + 1);
    const int g = lane >> 2, t = lane & 3;
    const int a_row = lane & 15, a_sel = (lane >> 4) * 8;
    const int b_row = lane & 7,  b_sel = ((lane >> 3) & 1) * 8;
    const int row0 = q0 + w * 16 + g;
    const int row1 = row0 + 8;
    const float scale = 0.08838834764831845f;

    float m0v = -1e30f, m1v = -1e30f, l0 = 0.f, l1 = 0.f;
    float acc[16][4];
#pragma unroll
    for (int i = 0; i < 16; i++)
#pragma unroll
        for (int j = 0; j < 4; j++) acc[i][j] = 0.f;

    for (int kb = 0; kb < nkb; kb++) {
        const int buf = kb & 1;
        if (kb + 1 < nkb) { LOAD_KV(kb + 1, buf ^ 1); CP_COMMIT(); CP_WAIT1(); }
        else CP_WAIT0();
        __syncthreads();
        const uint32_t Kh_s = KV0 + buf * 4 * FKV_BYTES;
        const uint32_t Kl_s = Kh_s + FKV_BYTES;
        const uint32_t Vh_s = Kh_s + 2 * FKV_BYTES;
        const uint32_t Vl_s = Kh_s + 3 * FKV_BYTES;

        float sc[8][4];
#pragma unroll
        for (int i = 0; i < 8; i++)
#pragma unroll
            for (int j = 0; j < 4; j++) sc[i][j] = 0.f;
#pragma unroll
        for (int ks = 0; ks < 8; ks++) {
            uint32_t aH[4], aL[4];
            uint32_t qaddr = Qh_s + (uint32_t)((w * 16 + a_row) * FSTRIDE + (ks * 16 + a_sel) * 2);
            ldmatrix_x4(aH, qaddr);
            ldmatrix_x4(aL, qaddr + FQ_BYTES);
#pragma unroll
            for (int ni = 0; ni < 8; ni++) {
                uint32_t bH[2], bL[2];
                uint32_t kaddr = Kh_s + (uint32_t)((ni * 8 + b_row) * FSTRIDE + (ks * 16 + b_sel) * 2);
                ldmatrix_x2(bH, kaddr);
                ldmatrix_x2(bL, kaddr + FKV_BYTES);
                mma_bf16(sc[ni], aH, bH);
                mma_bf16(sc[ni], aH, bL);
                mma_bf16(sc[ni], aL, bH);
            }
        }
        float mr0 = -1e30f, mr1 = -1e30f;
#pragma unroll
        for (int ni = 0; ni < 8; ni++) {
            int c0 = kb * 64 + ni * 8 + 2 * t, c1 = c0 + 1;
            sc[ni][0] = (c0 <= row0) ? sc[ni][0] * scale : -1e30f;
            sc[ni][1] = (c1 <= row0) ? sc[ni][1] * scale : -1e30f;
            sc[ni][2] = (c0 <= row1) ? sc[ni][2] * scale : -1e30f;
            sc[ni][3] = (c1 <= row1) ? sc[ni][3] * scale : -1e30f;
            mr0 = fmaxf(mr0, fmaxf(sc[ni][0], sc[ni][1]));
            mr1 = fmaxf(mr1, fmaxf(sc[ni][2], sc[ni][3]));
        }
        mr0 = fmaxf(mr0, __shfl_xor_sync(0xffffffffu, mr0, 1));
        mr0 = fmaxf(mr0, __shfl_xor_sync(0xffffffffu, mr0, 2));
        mr1 = fmaxf(mr1, __shfl_xor_sync(0xffffffffu, mr1, 1));
        mr1 = fmaxf(mr1, __shfl_xor_sync(0xffffffffu, mr1, 2));
        float mn0 = fmaxf(m0v, mr0), mn1 = fmaxf(m1v, mr1);
        float al0 = __expf(m0v - mn0), al1 = __expf(m1v - mn1);
        float ps0 = 0.f, ps1 = 0.f;
        uint32_t pH[4][4], pL[4][4];
#pragma unroll
        for (int ni = 0; ni < 8; ni++) {
            float p0 = __expf(sc[ni][0] - mn0), p1 = __expf(sc[ni][1] - mn0);
            float p2 = __expf(sc[ni][2] - mn1), p3 = __expf(sc[ni][3] - mn1);
            ps0 += p0 + p1; ps1 += p2 + p3;
            int ks = ni >> 1, hf = ni & 1;
            bf16 b0 = __float2bfloat16(p0), b1 = __float2bfloat16(p1);
            bf16 b2 = __float2bfloat16(p2), b3 = __float2bfloat16(p3);
            pH[ks][hf * 2 + 0] = ((uint32_t)__bfloat16_as_ushort(b1) << 16) | __bfloat16_as_ushort(b0);
            pH[ks][hf * 2 + 1] = ((uint32_t)__bfloat16_as_ushort(b3) << 16) | __bfloat16_as_ushort(b2);
            pL[ks][hf * 2 + 0] = pack2bf(p0 - __bfloat162float(b0), p1 - __bfloat162float(b1));
            pL[ks][hf * 2 + 1] = pack2bf(p2 - __bfloat162float(b2), p3 - __bfloat162float(b3));
        }
        ps0 += __shfl_xor_sync(0xffffffffu, ps0, 1);
        ps0 += __shfl_xor_sync(0xffffffffu, ps0, 2);
        ps1 += __shfl_xor_sync(0xffffffffu, ps1, 1);
        ps1 += __shfl_xor_sync(0xffffffffu, ps1, 2);
        l0 = l0 * al0 + ps0; l1 = l1 * al1 + ps1;
        m0v = mn0; m1v = mn1;
#pragma unroll
        for (int dj = 0; dj < 16; dj++) {
            acc[dj][0] *= al0; acc[dj][1] *= al0;
            acc[dj][2] *= al1; acc[dj][3] *= al1;
        }
#pragma unroll
        for (int ks = 0; ks < 4; ks++) {
#pragma unroll
            for (int dj = 0; dj < 16; dj++) {
                uint32_t bH[2], bL[2];
                uint32_t vaddr = Vh_s + (uint32_t)((ks * 16 + (lane & 15)) * FSTRIDE + dj * 16);
                ldmatrix_x2_trans(bH, vaddr);
                ldmatrix_x2_trans(bL, vaddr + FKV_BYTES);
                mma_bf16(acc[dj], pH[ks], bH);
                mma_bf16(acc[dj], pH[ks], bL);
                mma_bf16(acc[dj], pL[ks], bH);
            }
        }
        __syncthreads();
    }

    float inv0 = 1.f / l0, inv1 = 1.f / l1;
#pragma unroll
    for (int dj = 0; dj < 16; dj++) {
        int col = h * HD + dj * 8 + 2 * t;
        {
            float v0 = acc[dj][0] * inv0, v1 = acc[dj][1] * inv0;
            bf16 h0 = __float2bfloat16(v0), h1b = __float2bfloat16(v1);
            size_t o = (size_t)row0 * HDIM + col;
            *(uint32_t*)(oh + o) = ((uint32_t)__bfloat16_as_ushort(h1b) << 16) | __bfloat16_as_ushort(h0);
            *(uint32_t*)(ol + o) = pack2bf(v0 - __bfloat162float(h0), v1 - __bfloat162float(h1b));
        }
        {
            float v0 = acc[dj][2] * inv1, v1 = acc[dj][3] * inv1;
            bf16 h0 = __float2bfloat16(v0), h1b = __float2bfloat16(v1);
            size_t o = (size_t)row1 * HDIM + col;
            *(uint32_t*)(oh + o) = ((uint32_t)__bfloat16_as_ushort(h1b) << 16) | __bfloat16_as_ushort(h0);
            *(uint32_t*)(ol + o) = pack2bf(v0 - __bfloat162float(h0), v1 - __bfloat162float(h1b));
        }
    }
#undef LOAD_KV
}

// ---------------- SiLU(gate)*up -> bf16 hi/lo ----------------
__global__ void silu_mul_kernel(const float* __restrict__ gf, const float* __restrict__ uf,
                                bf16* __restrict__ gh, bf16* __restrict__ gl, int n4) {
    int i = blockIdx.x * blockDim.x + threadIdx.x;
    if (i >= n4) return;
    float4 a = ((const float4*)gf)[i];
    float4 b = ((const float4*)uf)[i];
    float r[4];
    r[0] = a.x / (1.f + __expf(-a.x)) * b.x;
    r[1] = a.y / (1.f + __expf(-a.y)) * b.y;
    r[2] = a.z / (1.f + __expf(-a.z)) * b.z;
    r[3] = a.w / (1.f + __expf(-a.w)) * b.w;
#pragma unroll
    for (int j = 0; j < 4; j++) {
        bf16 h = __float2bfloat16(r[j]);
        gh[i * 4 + j] = h;
        gl[i * 4 + j] = __float2bfloat16(r[j] - __bfloat162float(h));
    }
}

// ---------------- launch ----------------
extern "C" void kernel_launch(void* const* d_in, const int* in_sizes, int n_in,
                              void* d_out, int out_size) {
    const float* x    = (const float*)d_in[0];
    const float* cosb = (const float*)d_in[1];
    const float* sinb = (const float*)d_in[2];
    const float* wq   = (const float*)d_in[3];
    const float* wk   = (const float*)d_in[4];
    const float* wv   = (const float*)d_in[5];
    const float* wo   = (const float*)d_in[6];
    const float* w1   = (const float*)d_in[7];
    const float* w3   = (const float*)d_in[8];
    const float* w2   = (const float*)d_in[9];
    const float* v1   = (const float*)d_in[10];
    const float* v3   = (const float*)d_in[11];
    const float* v2   = (const float*)d_in[12];
    const float* anw  = (const float*)d_in[13];
    const float* fnw  = (const float*)d_in[14];
    const int*   vis  = (const int*)d_in[15];
    const int*   txt  = (const int*)d_in[16];

    float* out = (float*)d_out;
    float* res = out + (size_t)SQ * HDIM;

#define SYM(p, s) void* p##_; cudaGetSymbolAddress(&p##_, s);
    SYM(qf, g_qf) SYM(kf, g_kf) SYM(gate2, g_gate2) SYM(up2, g_up2)
    SYM(h1h, g_h1h) SYM(h1l, g_h1l) SYM(oh, g_oh) SYM(ol, g_ol) SYM(gh2, g_gh2) SYM(gl2, g_gl2)
    SYM(gidx, g_gidx)
    SYM(qh, g_qh) SYM(ql, g_ql) SYM(kh, g_kh) SYM(kl, g_kl) SYM(vh, g_vh) SYM(vl, g_vl)
    SYM(wqh, g_wqh) SYM(wql, g_wql) SYM(wkh, g_wkh) SYM(wkl, g_wkl)
    SYM(wvh, g_wvh) SYM(wvl, g_wvl) SYM(woh, g_woh) SYM(wol, g_wol)
    SYM(w1h, g_w1h) SYM(w1l, g_w1l) SYM(w3h, g_w3h) SYM(w3l, g_w3l)
    SYM(v1h, g_v1h) SYM(v1l, g_v1l) SYM(v3h, g_v3h) SYM(v3l, g_v3l)
    SYM(w2h, g_w2h) SYM(w2l, g_w2l) SYM(v2h, g_v2h) SYM(v2l, g_v2l)
#undef SYM

    cudaFuncSetAttribute(flash_kernel, cudaFuncAttributeMaxDynamicSharedMemorySize, FLASH_SMEM);
    cudaFuncSetAttribute(tgemm_kernel, cudaFuncAttributeMaxDynamicSharedMemorySize, GSMEM);
    cudaFuncSetAttribute(qkv_kernel,   cudaFuncAttributeMaxDynamicSharedMemorySize, GSMEM);
    cudaFuncSetAttribute(ffn_kernel,   cudaFuncAttributeMaxDynamicSharedMemorySize, GSMEM);
    cudaFuncSetAttribute(down_kernel,  cudaFuncAttributeMaxDynamicSharedMemorySize, GSMEM);

    // side stream + events (host-side objects only, created once)
    static cudaStream_t s2 = nullptr;
    static cudaEvent_t evFork = nullptr, evJoin1 = nullptr, evJoin2 = nullptr;
    if (s2 == nullptr) {
        cudaStreamCreateWithFlags(&s2, cudaStreamNonBlocking);
        cudaEventCreateWithFlags(&evFork, cudaEventDisableTiming);
        cudaEventCreateWithFlags(&evJoin1, cudaEventDisableTiming);
        cudaEventCreateWithFlags(&evJoin2, cudaEventDisableTiming);
    }

    // ---- fork all converts onto s2; rmsnorm runs concurrently on main ----
    cudaEventRecord(evFork, 0);
    cudaStreamWaitEvent(s2, evFork, 0);
    concat_idx_kernel<<<8, 256, 0, s2>>>(vis, txt, (int*)gidx_);
    wconvert_kernel<<<dim3(HDIM / 64, HDIM / 64), 256, 0, s2>>>(wq, (bf16*)wqh_, (bf16*)wql_, HDIM, HDIM);
    wconvert_kernel<<<dim3(1024 / 64, HDIM / 64), 256, 0, s2>>>(wk, (bf16*)wkh_, (bf16*)wkl_, HDIM, 1024);
    wconvert_kernel<<<dim3(1024 / 64, HDIM / 64), 256, 0, s2>>>(wv, (bf16*)wvh_, (bf16*)wvl_, HDIM, 1024);
    cudaEventRecord(evJoin1, s2);
    wconvert_kernel<<<dim3(HDIM / 64, HDIM / 64), 256, 0, s2>>>(wo, (bf16*)woh_, (bf16*)wol_, HDIM, HDIM);
    wconvert_kernel<<<dim3(FF / 64, HDIM / 64), 256, 0, s2>>>(w1, (bf16*)w1h_, (bf16*)w1l_, HDIM, FF);
    wconvert_kernel<<<dim3(FF / 64, HDIM / 64), 256, 0, s2>>>(w3, (bf16*)w3h_, (bf16*)w3l_, HDIM, FF);
    wconvert_kernel<<<dim3(FF / 64, HDIM / 64), 256, 0, s2>>>(v1, (bf16*)v1h_, (bf16*)v1l_, HDIM, FF);
    wconvert_kernel<<<dim3(FF / 64, HDIM / 64), 256, 0, s2>>>(v3, (bf16*)v3h_, (bf16*)v3l_, HDIM, FF);
    wconvert_kernel<<<dim3(HDIM / 64, FF / 64), 256, 0, s2>>>(w2, (bf16*)w2h_, (bf16*)w2l_, FF, HDIM);
    wconvert_kernel<<<dim3(HDIM / 64, FF / 64), 256, 0, s2>>>(v2, (bf16*)v2h_, (bf16*)v2l_, FF, HDIM);
    cudaEventRecord(evJoin2, s2);

    // ---- main stream ----
    // 1) attn rmsnorm -> bf16 hi/lo (concurrent with wq/wk/wv converts)
    rmsnorm_kernel<<<SQ, 256>>>(x, anw, (bf16*)h1h_, (bf16*)h1l_, nullptr);
    // join1: qkv needs wq/wk/wv
    cudaStreamWaitEvent(0, evJoin1, 0);
    // 2) QKV projections (fused; V writes bf16 hi/lo directly)
    qkv_kernel<<<dim3(32, SQ / 128), 128, GSMEM>>>((bf16*)h1h_, (bf16*)h1l_,
        (bf16*)wqh_, (bf16*)wql_, (bf16*)wkh_, (bf16*)wkl_, (bf16*)wvh_, (bf16*)wvl_,
        (float*)qf_, (float*)kf_, (bf16*)vh_, (bf16*)vl_);
    // 3) RoPE + convert q,k
    {
        int n = SQ * 24 * 64;
        ropeconv_kernel<<<(n + 255) / 256, 256>>>((float*)qf_, (float*)kf_, cosb, sinb,
            (bf16*)qh_, (bf16*)ql_, (bf16*)kh_, (bf16*)kl_);
    }
    // 4) attention (HMMA flash)
    flash_kernel<<<dim3(SQ / 128, NH), 256, FLASH_SMEM>>>((bf16*)qh_, (bf16*)ql_, (bf16*)kh_, (bf16*)kl_,
        (bf16*)vh_, (bf16*)vl_, (bf16*)oh_, (bf16*)ol_);
    // join2: wo/FF weights
    cudaStreamWaitEvent(0, evJoin2, 0);
    // 5) o-proj + residual -> res
    tgemm_kernel<<<dim3(HDIM / 128, SQ / 128), 128, GSMEM>>>((bf16*)oh_, (bf16*)ol_, (bf16*)woh_, (bf16*)wol_,
        res, HDIM, HDIM, nullptr, nullptr, x);
    // 6) ffn rmsnorm -> bf16 hi/lo + fp32 baseline into out
    rmsnorm_kernel<<<SQ, 256>>>(res, fnw, (bf16*)h1h_, (bf16*)h1l_, out);
    // 7) all four FF GEMMs fused (vision+text, gate+up)
    ffn_kernel<<<dim3(128, 16), 128, GSMEM>>>((bf16*)h1h_, (bf16*)h1l_,
        (bf16*)v1h_, (bf16*)v1l_, (bf16*)v3h_, (bf16*)v3l_,
        (bf16*)w1h_, (bf16*)w1l_, (bf16*)w3h_, (bf16*)w3l_,
        (float*)gate2_, (float*)up2_, (int*)gidx_);
    // 8) fused silu over both branches
    silu_mul_kernel<<<(2048 * FF / 4 + 255) / 256, 256>>>((float*)gate2_, (float*)up2_,
        (bf16*)gh2_, (bf16*)gl2_, 2048 * FF / 4);
    // 9) fused down-proj (w2 + v2), scatter to out
    down_kernel<<<dim3(16, 16), 128, GSMEM>>>((bf16*)gh2_, (bf16*)gl2_,
        (bf16*)v2h_, (bf16*)v2l_, (bf16*)w2h_, (bf16*)w2l_, out, (int*)gidx_);
}